// round 2
// baseline (speedup 1.0000x reference)
#include <cuda_runtime.h>
#include <math.h>

#define BB 64
#define TT 4096
#define CC 256
#define HH 4
#define HD 64
#define LN_EPS 1e-5f
#define NSPLIT 8

// scratch (no allocations allowed)
__device__ float g_scores[BB * HH * TT];            // 4 MB
__device__ float g_ctx[BB * NSPLIT * HH * CC];      // 2 MB

// ---------------------------------------------------------------------------
// Stage 1: scores[b][h][t] = w2[h] . tanh(x[b][t] @ W1[h] + b1[h])
// CTA: 64 t-rows of one batch. 256 threads as 16x16 (ty=t-block, tx=d-block).
// smem: x tile 64x256 (64KB) + per-head W1 256x64 (64KB) + reduction pad.
// ---------------------------------------------------------------------------
__global__ __launch_bounds__(256, 1) void k_scores(
    const float* __restrict__ x, const float* __restrict__ W1,
    const float* __restrict__ b1, const float* __restrict__ w2)
{
    extern __shared__ float sm[];
    float* x_s  = sm;                 // [64][256]
    float* w_s  = sm + 64 * CC;       // [256][64]  (c-major, d contiguous)
    float* sred = sm + 2 * 64 * CC;   // [64][17]

    const int t0  = blockIdx.x * 64;
    const int b   = blockIdx.y;
    const int tid = threadIdx.x;
    const int tx  = tid & 15;         // d-block 0..15 (4 d's each)
    const int ty  = tid >> 4;         // t-block 0..15 (4 t's each)

    // load x tile (coalesced float4)
    {
        const float4* xg = (const float4*)(x + ((size_t)b * TT + t0) * CC);
        float4* xs4 = (float4*)x_s;
        #pragma unroll
        for (int i = 0; i < 16; i++) xs4[tid + i * 256] = xg[tid + i * 256];
    }
    __syncthreads();

    for (int h = 0; h < HH; h++) {
        // load W1[h] (256x64 floats, natural layout)
        {
            const float4* wg = (const float4*)(W1 + (size_t)h * CC * HD);
            float4* ws4 = (float4*)w_s;
            #pragma unroll
            for (int i = 0; i < 16; i++) ws4[tid + i * 256] = wg[tid + i * 256];
        }
        __syncthreads();

        float acc[4][4] = {};
        #pragma unroll 2
        for (int c = 0; c < CC; c += 4) {
            float4 xa[4], wb[4];
            #pragma unroll
            for (int i = 0; i < 4; i++)
                xa[i] = *(const float4*)&x_s[(ty * 4 + i) * CC + c];
            #pragma unroll
            for (int j = 0; j < 4; j++)
                wb[j] = *(const float4*)&w_s[(c + j) * HD + tx * 4];
            #pragma unroll
            for (int jc = 0; jc < 4; jc++) {
                #pragma unroll
                for (int i = 0; i < 4; i++) {
                    float xv = (jc == 0) ? xa[i].x : (jc == 1) ? xa[i].y
                             : (jc == 2) ? xa[i].z : xa[i].w;
                    acc[i][0] += xv * wb[jc].x;
                    acc[i][1] += xv * wb[jc].y;
                    acc[i][2] += xv * wb[jc].z;
                    acc[i][3] += xv * wb[jc].w;
                }
            }
        }

        // epilogue: tanh + dot with w2, partial reduce across tx
        float b1v[4], w2v[4];
        #pragma unroll
        for (int j = 0; j < 4; j++) {
            b1v[j] = b1[h * HD + tx * 4 + j];
            w2v[j] = w2[h * HD + tx * 4 + j];
        }
        #pragma unroll
        for (int i = 0; i < 4; i++) {
            float sp = 0.f;
            #pragma unroll
            for (int j = 0; j < 4; j++)
                sp += tanhf(acc[i][j] + b1v[j]) * w2v[j];
            sred[(ty * 4 + i) * 17 + tx] = sp;
        }
        __syncthreads();
        if (tid < 64) {
            float s = 0.f;
            #pragma unroll
            for (int k = 0; k < 16; k++) s += sred[tid * 17 + k];
            g_scores[((size_t)(b * HH + h)) * TT + t0 + tid] = s;
        }
        __syncthreads();
    }
}

// ---------------------------------------------------------------------------
// Stage 2: softmax over T per (b,h); writes weights into d_out region.
// ---------------------------------------------------------------------------
__global__ __launch_bounds__(256, 1) void k_softmax(float* __restrict__ wout)
{
    const int bh  = blockIdx.x;
    const int tid = threadIdx.x;
    const float* s = g_scores + (size_t)bh * TT;
    float*       w = wout     + (size_t)bh * TT;
    __shared__ float red[256];

    float loc[16];
    float m = -1e30f;
    #pragma unroll
    for (int i = 0; i < 16; i++) {
        loc[i] = s[tid + i * 256];
        m = fmaxf(m, loc[i]);
    }
    red[tid] = m; __syncthreads();
    for (int st = 128; st > 0; st >>= 1) {
        if (tid < st) red[tid] = fmaxf(red[tid], red[tid + st]);
        __syncthreads();
    }
    m = red[0]; __syncthreads();

    float sum = 0.f;
    #pragma unroll
    for (int i = 0; i < 16; i++) {
        loc[i] = expf(loc[i] - m);
        sum += loc[i];
    }
    red[tid] = sum; __syncthreads();
    for (int st = 128; st > 0; st >>= 1) {
        if (tid < st) red[tid] += red[tid + st];
        __syncthreads();
    }
    const float inv = 1.f / red[0];
    #pragma unroll
    for (int i = 0; i < 16; i++) w[tid + i * 256] = loc[i] * inv;
}

// ---------------------------------------------------------------------------
// Stage 3: partial contexts: ctx[b][split][h][c] = sum_{t in split} w*x
// grid (NSPLIT, B), thread = channel c.
// ---------------------------------------------------------------------------
__global__ __launch_bounds__(256, 1) void k_ctx(
    const float* __restrict__ x, const float* __restrict__ wts)
{
    const int split = blockIdx.x;
    const int b     = blockIdx.y;
    const int tid   = threadIdx.x;
    __shared__ float ws[HH][128];
    float acc[HH] = {};
    const int tbase = split * (TT / NSPLIT);  // 512 rows per split

    for (int ch = 0; ch < (TT / NSPLIT) / 128; ch++) {
        const int t0 = tbase + ch * 128;
        for (int i = tid; i < HH * 128; i += 256) {
            int hh = i >> 7, tt = i & 127;
            ws[hh][tt] = wts[((size_t)(b * HH + hh)) * TT + t0 + tt];
        }
        __syncthreads();
        const float* xp = x + ((size_t)b * TT + t0) * CC + tid;
        #pragma unroll 4
        for (int tt = 0; tt < 128; tt++) {
            float xv = xp[(size_t)tt * CC];
            #pragma unroll
            for (int h = 0; h < HH; h++) acc[h] += ws[h][tt] * xv;
        }
        __syncthreads();
    }
    #pragma unroll
    for (int h = 0; h < HH; h++)
        g_ctx[(((size_t)(b * NSPLIT + split)) * HH + h) * CC + tid] = acc[h];
}

// ---------------------------------------------------------------------------
// Stage 4: reduce splits, out = multi @ Wo^T + bo, LayerNorm. grid = B.
// ---------------------------------------------------------------------------
__global__ __launch_bounds__(256, 1) void k_out(
    const float* __restrict__ Wo, const float* __restrict__ bo,
    const float* __restrict__ gamma, const float* __restrict__ beta,
    float* __restrict__ out)
{
    const int b   = blockIdx.x;
    const int tid = threadIdx.x;
    __shared__ float multi[HH * CC];
    __shared__ float red[256];

    for (int n = tid; n < HH * CC; n += 256) {
        float s = 0.f;
        #pragma unroll
        for (int sp = 0; sp < NSPLIT; sp++)
            s += g_ctx[((size_t)(b * NSPLIT + sp)) * HH * CC + n];
        multi[n] = s;
    }
    __syncthreads();

    const float* wr = Wo + (size_t)tid * (HH * CC);
    float v = bo[tid];
    #pragma unroll 8
    for (int n = 0; n < HH * CC; n += 4) {
        float4 w4 = *(const float4*)&wr[n];
        v += w4.x * multi[n] + w4.y * multi[n + 1]
           + w4.z * multi[n + 2] + w4.w * multi[n + 3];
    }

    red[tid] = v; __syncthreads();
    for (int st = 128; st > 0; st >>= 1) {
        if (tid < st) red[tid] += red[tid + st];
        __syncthreads();
    }
    const float mu = red[0] * (1.f / CC); __syncthreads();
    const float d = v - mu;
    red[tid] = d * d; __syncthreads();
    for (int st = 128; st > 0; st >>= 1) {
        if (tid < st) red[tid] += red[tid + st];
        __syncthreads();
    }
    const float var = red[0] * (1.f / CC);
    out[(size_t)b * CC + tid] = d * rsqrtf(var + LN_EPS) * gamma[tid] + beta[tid];
}

// ---------------------------------------------------------------------------
extern "C" void kernel_launch(void* const* d_in, const int* in_sizes, int n_in,
                              void* d_out, int out_size)
{
    const float* x     = (const float*)d_in[0];
    const float* W1    = (const float*)d_in[1];
    const float* b1    = (const float*)d_in[2];
    const float* w2    = (const float*)d_in[3];
    const float* Wo    = (const float*)d_in[4];
    const float* bo    = (const float*)d_in[5];
    const float* gamma = (const float*)d_in[6];
    const float* beta  = (const float*)d_in[7];

    float* out = (float*)d_out;           // (B, C)
    float* wts = out + BB * CC;           // (B, H, T)

    const int smem1 = (2 * 64 * CC + 64 * 17) * (int)sizeof(float);  // ~135 KB
    cudaFuncSetAttribute(k_scores, cudaFuncAttributeMaxDynamicSharedMemorySize, smem1);

    k_scores <<<dim3(TT / 64, BB), 256, smem1>>>(x, W1, b1, w2);
    k_softmax<<<BB * HH, 256>>>(wts);
    k_ctx    <<<dim3(NSPLIT, BB), 256>>>(x, wts);
    k_out    <<<BB, 256>>>(Wo, bo, gamma, beta, out);
}

// round 5
// speedup vs baseline: 3.7106x; 3.7106x over previous
#include <cuda_runtime.h>
#include <cuda_fp16.h>
#include <math.h>
#include <stdint.h>

#define BB 64
#define TT 4096
#define CC 256
#define HH 4
#define HD 64
#define LN_EPS 1e-5f
#define NSPLIT 16

// W image: per head 64 rows x 264 (padded) fp16 = 33792 B = 2112 uint4
#define WPAD 264
#define W_U4_PER_H 2112

// smem layout for k_scores_mma (bytes)
#define SMEM_X 0
#define SMEM_W (128 * WPAD * 2)                 // 67584
#define SMEM_SC_TOTAL (SMEM_W + 64 * WPAD * 2)  // 101376

// ---------------------------------------------------------------------------
// scratch globals (no allocations allowed)
// ---------------------------------------------------------------------------
__device__ float g_scores[BB * HH * TT];        // 4 MB (reused as raw-out later)
__device__ float g_ctx[BB * NSPLIT * HH * CC];  // 16 MB
__device__ uint4 g_wimg[HH * W_U4_PER_H];       // fp16 W1^T images, padded rows

__device__ __forceinline__ uint32_t smem_to_u32(const void* p) {
    uint32_t a;
    asm("{ .reg .u64 t; cvta.to.shared.u64 t, %1; cvt.u32.u64 %0, t; }" : "=r"(a) : "l"(p));
    return a;
}

#define LDMATRIX_X4(r0, r1, r2, r3, addr) \
    asm volatile("ldmatrix.sync.aligned.m8n8.x4.shared.b16 {%0,%1,%2,%3}, [%4];" \
                 : "=r"(r0), "=r"(r1), "=r"(r2), "=r"(r3) : "r"(addr))

#define MMA_16816(c, a0, a1, a2, a3, b0, b1) \
    asm volatile("mma.sync.aligned.m16n8k16.row.col.f32.f16.f16.f32 " \
                 "{%0,%1,%2,%3}, {%4,%5,%6,%7}, {%8,%9}, {%0,%1,%2,%3};" \
                 : "+f"((c)[0]), "+f"((c)[1]), "+f"((c)[2]), "+f"((c)[3]) \
                 : "r"(a0), "r"(a1), "r"(a2), "r"(a3), "r"(b0), "r"(b1))

// ---------------------------------------------------------------------------
// Prep: W1[h] (C x HD, d contiguous) -> fp16 (d-row, c-col) padded image
// ---------------------------------------------------------------------------
__global__ void k_prepw(const float* __restrict__ W1) {
    const int h = blockIdx.x;
    __half* img = (__half*)g_wimg + (size_t)h * (64 * WPAD);
    for (int i = threadIdx.x; i < CC * HD; i += blockDim.x) {
        int c = i >> 6, d = i & 63;
        img[d * WPAD + c] = __float2half_rn(W1[(size_t)h * CC * HD + i]);
    }
}

// ---------------------------------------------------------------------------
// Stage 1 (mma.sync fp16): scores[b][h][t] = w2[h].tanh(x[b][t]@W1[h]+b1[h])
// CTA = 128 t-rows x 1 batch; 8 warps, warp w owns rows [16w,16w+16), N=64.
// ---------------------------------------------------------------------------
__global__ __launch_bounds__(256, 2) void k_scores_mma(
    const float* __restrict__ x, const float* __restrict__ b1,
    const float* __restrict__ w2)
{
    extern __shared__ char smem[];
    const int tid = threadIdx.x;
    const int wid = tid >> 5;
    const int lid = tid & 31;
    const int t0 = blockIdx.x * 128;
    const int b  = blockIdx.y;
    const uint32_t sbase = smem_to_u32(smem);

    // ---- load X tile (128x256 f32), convert to fp16, padded smem ----
    {
        const float4* xg = (const float4*)(x + ((size_t)b * TT + t0) * CC);
        #pragma unroll
        for (int i = 0; i < 32; i++) {
            int idx = tid + i * 256;
            int m = idx >> 6, c4 = idx & 63;
            float4 v = xg[idx];
            __half2 h0 = __floats2half2_rn(v.x, v.y);
            __half2 h1 = __floats2half2_rn(v.z, v.w);
            uint2 p;
            p.x = *(const uint32_t*)&h0;
            p.y = *(const uint32_t*)&h1;
            *(uint2*)(smem + SMEM_X + m * (WPAD * 2) + c4 * 8) = p;
        }
    }

    // ---- per-lane ldmatrix base addresses ----
    const int lq = lid >> 3;      // quad 0..3
    const int lr = lid & 7;
    // A 16x16 tile: quads -> (rows 0-7,k-lo),(rows 8-15,k-lo),(rows 0-7,k-hi),(rows 8-15,k-hi)
    const uint32_t a_base = sbase + SMEM_X +
        ((uint32_t)(wid * 16 + lr + ((lq & 1) << 3)) * (WPAD * 2)) + (((lq >> 1) << 3) << 1);
    // B x4 group g covers n-tiles {2g,2g+1}: quads -> (nt,k-lo),(nt,k-hi),(nt+1,k-lo),(nt+1,k-hi)
    uint32_t b_base[4];
    #pragma unroll
    for (int g = 0; g < 4; g++)
        b_base[g] = sbase + SMEM_W +
            ((uint32_t)((g * 2 + (lq >> 1)) * 8 + lr) * (WPAD * 2)) + (((lq & 1) << 3) << 1);

    const int d0 = (lid & 3) * 2;

    for (int h = 0; h < HH; h++) {
        __syncthreads();  // previous head done reading W smem
        {
            const uint4* src = g_wimg + h * W_U4_PER_H;
            uint4* dst = (uint4*)(smem + SMEM_W);
            #pragma unroll
            for (int i = 0; i < 9; i++) {       // 9*256 = 2304 >= 2112
                int j = tid + i * 256;
                if (j < W_U4_PER_H) dst[j] = src[j];
            }
        }
        __syncthreads();  // X (first head) + W ready

        float c[8][4];
        #pragma unroll
        for (int nt = 0; nt < 8; nt++)
            #pragma unroll
            for (int j = 0; j < 4; j++) c[nt][j] = 0.f;

        #pragma unroll 4
        for (int ks = 0; ks < 16; ks++) {
            uint32_t a0, a1, a2, a3;
            LDMATRIX_X4(a0, a1, a2, a3, a_base + ks * 32);
            uint32_t br[16];
            #pragma unroll
            for (int g = 0; g < 4; g++)
                LDMATRIX_X4(br[g * 4], br[g * 4 + 1], br[g * 4 + 2], br[g * 4 + 3],
                            b_base[g] + ks * 32);
            #pragma unroll
            for (int nt = 0; nt < 8; nt++) {
                int bi = (nt >> 1) * 4 + (nt & 1) * 2;
                MMA_16816(c[nt], a0, a1, a2, a3, br[bi], br[bi + 1]);
            }
        }

        // ---- epilogue: + b1, tanh, dot w2, reduce over lane quads ----
        float s0 = 0.f, s1 = 0.f;
        #pragma unroll
        for (int nt = 0; nt < 8; nt++) {
            #pragma unroll
            for (int j = 0; j < 2; j++) {
                int d = nt * 8 + d0 + j;
                float bb = __ldg(&b1[h * HD + d]);
                float ww = __ldg(&w2[h * HD + d]);
                s0 += tanhf(c[nt][j] + bb) * ww;       // row = groupID
                s1 += tanhf(c[nt][2 + j] + bb) * ww;   // row = groupID + 8
            }
        }
        s0 += __shfl_xor_sync(0xffffffffu, s0, 1);
        s0 += __shfl_xor_sync(0xffffffffu, s0, 2);
        s1 += __shfl_xor_sync(0xffffffffu, s1, 1);
        s1 += __shfl_xor_sync(0xffffffffu, s1, 2);
        if ((lid & 3) == 0) {
            int r = wid * 16 + (lid >> 2);
            float* sc = g_scores + ((size_t)(b * HH + h)) * TT + t0;
            sc[r]     = s0;
            sc[r + 8] = s1;
        }
    }
}

// ---------------------------------------------------------------------------
// Stage 2: softmax over T per (b,h); writes weights into d_out region.
// ---------------------------------------------------------------------------
__global__ __launch_bounds__(256, 1) void k_softmax(float* __restrict__ wout)
{
    const int bh  = blockIdx.x;
    const int tid = threadIdx.x;
    const float* s = g_scores + (size_t)bh * TT;
    float*       w = wout     + (size_t)bh * TT;
    __shared__ float red[256];

    float loc[16];
    float m = -1e30f;
    #pragma unroll
    for (int i = 0; i < 16; i++) { loc[i] = s[tid + i * 256]; m = fmaxf(m, loc[i]); }
    red[tid] = m; __syncthreads();
    for (int st = 128; st > 0; st >>= 1) {
        if (tid < st) red[tid] = fmaxf(red[tid], red[tid + st]);
        __syncthreads();
    }
    m = red[0]; __syncthreads();

    float sum = 0.f;
    #pragma unroll
    for (int i = 0; i < 16; i++) { loc[i] = expf(loc[i] - m); sum += loc[i]; }
    red[tid] = sum; __syncthreads();
    for (int st = 128; st > 0; st >>= 1) {
        if (tid < st) red[tid] += red[tid + st];
        __syncthreads();
    }
    const float inv = 1.f / red[0];
    #pragma unroll
    for (int i = 0; i < 16; i++) w[tid + i * 256] = loc[i] * inv;
}

// ---------------------------------------------------------------------------
// Stage 3: partial contexts: ctx[b][split][h][c] = sum_{t in split} w*x
// ---------------------------------------------------------------------------
__global__ __launch_bounds__(256, 1) void k_ctx(
    const float* __restrict__ x, const float* __restrict__ wts)
{
    const int split = blockIdx.x;
    const int b     = blockIdx.y;
    const int tid   = threadIdx.x;
    __shared__ float ws[HH][128];
    float acc[HH] = {};
    const int tbase = split * (TT / NSPLIT);

    for (int ch = 0; ch < (TT / NSPLIT) / 128; ch++) {
        const int t0 = tbase + ch * 128;
        for (int i = tid; i < HH * 128; i += 256) {
            int hh = i >> 7, tt = i & 127;
            ws[hh][tt] = wts[((size_t)(b * HH + hh)) * TT + t0 + tt];
        }
        __syncthreads();
        const float* xp = x + ((size_t)b * TT + t0) * CC + tid;
        #pragma unroll 4
        for (int tt = 0; tt < 128; tt++) {
            float xv = xp[(size_t)tt * CC];
            #pragma unroll
            for (int h = 0; h < HH; h++) acc[h] += ws[h][tt] * xv;
        }
        __syncthreads();
    }
    #pragma unroll
    for (int h = 0; h < HH; h++)
        g_ctx[(((size_t)(b * NSPLIT + split)) * HH + h) * CC + tid] = acc[h];
}

// ---------------------------------------------------------------------------
// Stage 4a: projection. grid (8 col-tiles, B). Raw out -> g_scores scratch.
// ---------------------------------------------------------------------------
__global__ __launch_bounds__(256, 1) void k_proj(
    const float* __restrict__ Wo, const float* __restrict__ bo)
{
    const int ct  = blockIdx.x;   // 0..7 (32 cols each)
    const int b   = blockIdx.y;
    const int tid = threadIdx.x;
    __shared__ float multi[HH * CC];

    for (int n = tid; n < HH * CC; n += 256) {
        float s = 0.f;
        #pragma unroll
        for (int sp = 0; sp < NSPLIT; sp++)
            s += g_ctx[((size_t)(b * NSPLIT + sp)) * (HH * CC) + n];
        multi[n] = s;
    }
    __syncthreads();

    const int col   = ct * 32 + (tid >> 3);
    const int lane8 = tid & 7;
    const float* wr = Wo + (size_t)col * (HH * CC);
    float v = 0.f;
    #pragma unroll 4
    for (int k = lane8 * 4; k < HH * CC; k += 32) {
        float4 w4 = *(const float4*)&wr[k];
        v += w4.x * multi[k] + w4.y * multi[k + 1] + w4.z * multi[k + 2] + w4.w * multi[k + 3];
    }
    v += __shfl_down_sync(0xffffffffu, v, 4, 8);
    v += __shfl_down_sync(0xffffffffu, v, 2, 8);
    v += __shfl_down_sync(0xffffffffu, v, 1, 8);
    if (lane8 == 0) g_scores[(size_t)b * CC + col] = v + bo[col];
}

// ---------------------------------------------------------------------------
// Stage 4b: LayerNorm. grid = B.
// ---------------------------------------------------------------------------
__global__ __launch_bounds__(256, 1) void k_ln(
    const float* __restrict__ gamma, const float* __restrict__ beta,
    float* __restrict__ out)
{
    const int b   = blockIdx.x;
    const int tid = threadIdx.x;
    __shared__ float red[256];
    const float v = g_scores[(size_t)b * CC + tid];

    red[tid] = v; __syncthreads();
    for (int st = 128; st > 0; st >>= 1) {
        if (tid < st) red[tid] += red[tid + st];
        __syncthreads();
    }
    const float mu = red[0] * (1.f / CC); __syncthreads();
    const float d = v - mu;
    red[tid] = d * d; __syncthreads();
    for (int st = 128; st > 0; st >>= 1) {
        if (tid < st) red[tid] += red[tid + st];
        __syncthreads();
    }
    const float var = red[0] * (1.f / CC);
    out[(size_t)b * CC + tid] = d * rsqrtf(var + LN_EPS) * gamma[tid] + beta[tid];
}

// ---------------------------------------------------------------------------
extern "C" void kernel_launch(void* const* d_in, const int* in_sizes, int n_in,
                              void* d_out, int out_size)
{
    const float* x     = (const float*)d_in[0];
    const float* W1    = (const float*)d_in[1];
    const float* b1    = (const float*)d_in[2];
    const float* w2    = (const float*)d_in[3];
    const float* Wo    = (const float*)d_in[4];
    const float* bo    = (const float*)d_in[5];
    const float* gamma = (const float*)d_in[6];
    const float* beta  = (const float*)d_in[7];

    float* out = (float*)d_out;           // (B, C)
    float* wts = out + BB * CC;           // (B, H, T)

    cudaFuncSetAttribute(k_scores_mma, cudaFuncAttributeMaxDynamicSharedMemorySize,
                         SMEM_SC_TOTAL);

    k_prepw     <<<HH, 256>>>(W1);
    k_scores_mma<<<dim3(TT / 128, BB), 256, SMEM_SC_TOTAL>>>(x, b1, w2);
    k_softmax   <<<BB * HH, 256>>>(wts);
    k_ctx       <<<dim3(NSPLIT, BB), 256>>>(x, wts);
    k_proj      <<<dim3(8, BB), 256>>>(Wo, bo);
    k_ln        <<<BB, 256>>>(gamma, beta, out);
}

// round 6
// speedup vs baseline: 4.4842x; 1.2085x over previous
#include <cuda_runtime.h>
#include <cuda_fp16.h>
#include <math.h>
#include <stdint.h>

#define BB 64
#define TT 4096
#define CC 256
#define HH 4
#define HD 64
#define LN_EPS 1e-5f
#define NSPLIT 16
#define TS (TT / NSPLIT)   // 256 t-rows per split

// W image: per head 64 rows x 264 (padded) fp16 = 33792 B = 2112 uint4
#define WPAD 264
#define W_U4_PER_H 2112

// smem layout for k_scores_mma (bytes)
#define SMEM_X 0
#define SMEM_W (128 * WPAD * 2)                 // 67584
#define SMEM_SC_TOTAL (SMEM_W + 64 * WPAD * 2)  // 101376

// ---------------------------------------------------------------------------
// scratch globals (no allocations allowed)
// ---------------------------------------------------------------------------
__device__ float g_scores[BB * HH * TT];        // 4 MB (reused as raw-out later)
__device__ float g_ctx[BB * NSPLIT * HH * CC];  // 16 MB
__device__ uint4 g_wimg[HH * W_U4_PER_H];       // fp16 W1^T images, padded rows

__device__ __forceinline__ uint32_t smem_to_u32(const void* p) {
    uint32_t a;
    asm("{ .reg .u64 t; cvta.to.shared.u64 t, %1; cvt.u32.u64 %0, t; }" : "=r"(a) : "l"(p));
    return a;
}
__device__ __forceinline__ float tanh_fast(float x) {
    float y;
    asm("tanh.approx.f32 %0, %1;" : "=f"(y) : "f"(x));
    return y;
}

#define LDMATRIX_X4(r0, r1, r2, r3, addr) \
    asm volatile("ldmatrix.sync.aligned.m8n8.x4.shared.b16 {%0,%1,%2,%3}, [%4];" \
                 : "=r"(r0), "=r"(r1), "=r"(r2), "=r"(r3) : "r"(addr))

#define MMA_16816(c, a0, a1, a2, a3, b0, b1) \
    asm volatile("mma.sync.aligned.m16n8k16.row.col.f32.f16.f16.f32 " \
                 "{%0,%1,%2,%3}, {%4,%5,%6,%7}, {%8,%9}, {%0,%1,%2,%3};" \
                 : "+f"((c)[0]), "+f"((c)[1]), "+f"((c)[2]), "+f"((c)[3]) \
                 : "r"(a0), "r"(a1), "r"(a2), "r"(a3), "r"(b0), "r"(b1))

// ---------------------------------------------------------------------------
// Prep: W1[h] (C x HD, d contiguous) -> fp16 (d-row, c-col) padded image
// ---------------------------------------------------------------------------
__global__ void k_prepw(const float* __restrict__ W1) {
    const int h = blockIdx.x;
    __half* img = (__half*)g_wimg + (size_t)h * (64 * WPAD);
    for (int i = threadIdx.x; i < CC * HD; i += blockDim.x) {
        int c = i >> 6, d = i & 63;
        img[d * WPAD + c] = __float2half_rn(W1[(size_t)h * CC * HD + i]);
    }
}

// ---------------------------------------------------------------------------
// Stage 1 (mma.sync fp16): scores[b][h][t] = w2[h].tanh(x[b][t]@W1[h]+b1[h])
// CTA = 128 t-rows x 1 batch; 8 warps, warp w owns rows [16w,16w+16), N=64.
// ---------------------------------------------------------------------------
__global__ __launch_bounds__(256, 2) void k_scores_mma(
    const float* __restrict__ x, const float* __restrict__ b1,
    const float* __restrict__ w2)
{
    extern __shared__ char smem[];
    const int tid = threadIdx.x;
    const int wid = tid >> 5;
    const int lid = tid & 31;
    const int t0 = blockIdx.x * 128;
    const int b  = blockIdx.y;
    const uint32_t sbase = smem_to_u32(smem);

    // ---- load X tile (128x256 f32), convert to fp16, padded smem ----
    {
        const float4* xg = (const float4*)(x + ((size_t)b * TT + t0) * CC);
        #pragma unroll
        for (int i = 0; i < 32; i++) {
            int idx = tid + i * 256;
            int m = idx >> 6, c4 = idx & 63;
            float4 v = xg[idx];
            __half2 h0 = __floats2half2_rn(v.x, v.y);
            __half2 h1 = __floats2half2_rn(v.z, v.w);
            uint2 p;
            p.x = *(const uint32_t*)&h0;
            p.y = *(const uint32_t*)&h1;
            *(uint2*)(smem + SMEM_X + m * (WPAD * 2) + c4 * 8) = p;
        }
    }

    // ---- per-lane ldmatrix base addresses ----
    const int lq = lid >> 3;      // quad 0..3
    const int lr = lid & 7;
    const uint32_t a_base = sbase + SMEM_X +
        ((uint32_t)(wid * 16 + lr + ((lq & 1) << 3)) * (WPAD * 2)) + (((lq >> 1) << 3) << 1);
    uint32_t b_base[4];
    #pragma unroll
    for (int g = 0; g < 4; g++)
        b_base[g] = sbase + SMEM_W +
            ((uint32_t)((g * 2 + (lq >> 1)) * 8 + lr) * (WPAD * 2)) + (((lq & 1) << 3) << 1);

    const int d0 = (lid & 3) * 2;

    for (int h = 0; h < HH; h++) {
        __syncthreads();  // previous head done reading W smem
        {
            const uint4* src = g_wimg + h * W_U4_PER_H;
            uint4* dst = (uint4*)(smem + SMEM_W);
            #pragma unroll
            for (int i = 0; i < 9; i++) {       // 9*256 = 2304 >= 2112
                int j = tid + i * 256;
                if (j < W_U4_PER_H) dst[j] = src[j];
            }
        }
        __syncthreads();  // X + W ready

        float c[8][4];
        #pragma unroll
        for (int nt = 0; nt < 8; nt++)
            #pragma unroll
            for (int j = 0; j < 4; j++) c[nt][j] = 0.f;

        #pragma unroll 4
        for (int ks = 0; ks < 16; ks++) {
            uint32_t a0, a1, a2, a3;
            LDMATRIX_X4(a0, a1, a2, a3, a_base + ks * 32);
            uint32_t br[16];
            #pragma unroll
            for (int g = 0; g < 4; g++)
                LDMATRIX_X4(br[g * 4], br[g * 4 + 1], br[g * 4 + 2], br[g * 4 + 3],
                            b_base[g] + ks * 32);
            #pragma unroll
            for (int nt = 0; nt < 8; nt++) {
                int bi = (nt >> 1) * 4 + (nt & 1) * 2;
                MMA_16816(c[nt], a0, a1, a2, a3, br[bi], br[bi + 1]);
            }
        }

        // ---- epilogue: + b1, HW tanh, dot w2, reduce over lane quads ----
        float s0 = 0.f, s1 = 0.f;
        #pragma unroll
        for (int nt = 0; nt < 8; nt++) {
            #pragma unroll
            for (int j = 0; j < 2; j++) {
                int d = nt * 8 + d0 + j;
                float bb = __ldg(&b1[h * HD + d]);
                float ww = __ldg(&w2[h * HD + d]);
                s0 += tanh_fast(c[nt][j] + bb) * ww;       // row = groupID
                s1 += tanh_fast(c[nt][2 + j] + bb) * ww;   // row = groupID + 8
            }
        }
        s0 += __shfl_xor_sync(0xffffffffu, s0, 1);
        s0 += __shfl_xor_sync(0xffffffffu, s0, 2);
        s1 += __shfl_xor_sync(0xffffffffu, s1, 1);
        s1 += __shfl_xor_sync(0xffffffffu, s1, 2);
        if ((lid & 3) == 0) {
            int r = wid * 16 + (lid >> 2);
            float* sc = g_scores + ((size_t)(b * HH + h)) * TT + t0;
            sc[r]     = s0;
            sc[r + 8] = s1;
        }
    }
}

// ---------------------------------------------------------------------------
// Stage 2: softmax over T per (b,h); writes weights into d_out region.
// ---------------------------------------------------------------------------
__global__ __launch_bounds__(256, 1) void k_softmax(float* __restrict__ wout)
{
    const int bh  = blockIdx.x;
    const int tid = threadIdx.x;
    const float* s = g_scores + (size_t)bh * TT;
    float*       w = wout     + (size_t)bh * TT;
    __shared__ float red[256];

    float loc[16];
    float m = -1e30f;
    #pragma unroll
    for (int i = 0; i < 16; i++) { loc[i] = s[tid + i * 256]; m = fmaxf(m, loc[i]); }
    red[tid] = m; __syncthreads();
    for (int st = 128; st > 0; st >>= 1) {
        if (tid < st) red[tid] = fmaxf(red[tid], red[tid + st]);
        __syncthreads();
    }
    m = red[0]; __syncthreads();

    float sum = 0.f;
    #pragma unroll
    for (int i = 0; i < 16; i++) { loc[i] = __expf(loc[i] - m); sum += loc[i]; }
    red[tid] = sum; __syncthreads();
    for (int st = 128; st > 0; st >>= 1) {
        if (tid < st) red[tid] += red[tid + st];
        __syncthreads();
    }
    const float inv = 1.f / red[0];
    #pragma unroll
    for (int i = 0; i < 16; i++) w[tid + i * 256] = loc[i] * inv;
}

// ---------------------------------------------------------------------------
// Stage 3: partial contexts: ctx[b][split][h][c] = sum_{t in split} w*x
// 256 threads = 4 row-groups x 64 channel-quads; float4 loads for MLP.
// ---------------------------------------------------------------------------
__global__ __launch_bounds__(256, 2) void k_ctx(
    const float* __restrict__ x, const float* __restrict__ wts)
{
    const int split = blockIdx.x;
    const int b     = blockIdx.y;
    const int tid   = threadIdx.x;
    const int grp   = tid >> 6;     // 0..3
    const int ch    = tid & 63;     // float4-column
    __shared__ float ws[HH][TS];            // 4 KB
    __shared__ float red[4][HH][CC];        // 16 KB

    const int tbase = split * TS;
    for (int i = tid; i < HH * TS; i += 256) {
        int hh = i >> 8, tt = i & (TS - 1);
        ws[hh][tt] = wts[((size_t)(b * HH + hh)) * TT + tbase + tt];
    }
    __syncthreads();

    float4 acc[HH] = {};
    const float4* xp = (const float4*)(x + ((size_t)b * TT + tbase) * CC) + ch;
    #pragma unroll 4
    for (int tt = grp; tt < TS; tt += 4) {
        float4 xv = xp[(size_t)tt * 64];
        #pragma unroll
        for (int h = 0; h < HH; h++) {
            float w = ws[h][tt];
            acc[h].x += w * xv.x; acc[h].y += w * xv.y;
            acc[h].z += w * xv.z; acc[h].w += w * xv.w;
        }
    }
    #pragma unroll
    for (int h = 0; h < HH; h++)
        *(float4*)&red[grp][h][ch * 4] = acc[h];
    __syncthreads();

    for (int n = tid; n < HH * CC; n += 256) {
        int h = n >> 8, c = n & 255;
        float s = red[0][h][c] + red[1][h][c] + red[2][h][c] + red[3][h][c];
        g_ctx[(((size_t)(b * NSPLIT + split)) * HH + h) * CC + c] = s;
    }
}

// ---------------------------------------------------------------------------
// Stage 4a: projection. grid (8 col-tiles, B). Raw out -> g_scores scratch.
// ---------------------------------------------------------------------------
__global__ __launch_bounds__(256, 1) void k_proj(
    const float* __restrict__ Wo, const float* __restrict__ bo)
{
    const int ct  = blockIdx.x;   // 0..7 (32 cols each)
    const int b   = blockIdx.y;
    const int tid = threadIdx.x;
    __shared__ float multi[HH * CC];

    for (int n = tid; n < HH * CC; n += 256) {
        float s = 0.f;
        #pragma unroll
        for (int sp = 0; sp < NSPLIT; sp++)
            s += g_ctx[((size_t)(b * NSPLIT + sp)) * (HH * CC) + n];
        multi[n] = s;
    }
    __syncthreads();

    const int col   = ct * 32 + (tid >> 3);
    const int lane8 = tid & 7;
    const float* wr = Wo + (size_t)col * (HH * CC);
    float v = 0.f;
    #pragma unroll 4
    for (int k = lane8 * 4; k < HH * CC; k += 32) {
        float4 w4 = *(const float4*)&wr[k];
        v += w4.x * multi[k] + w4.y * multi[k + 1] + w4.z * multi[k + 2] + w4.w * multi[k + 3];
    }
    v += __shfl_down_sync(0xffffffffu, v, 4, 8);
    v += __shfl_down_sync(0xffffffffu, v, 2, 8);
    v += __shfl_down_sync(0xffffffffu, v, 1, 8);
    if (lane8 == 0) g_scores[(size_t)b * CC + col] = v + bo[col];
}

// ---------------------------------------------------------------------------
// Stage 4b: LayerNorm. grid = B.
// ---------------------------------------------------------------------------
__global__ __launch_bounds__(256, 1) void k_ln(
    const float* __restrict__ gamma, const float* __restrict__ beta,
    float* __restrict__ out)
{
    const int b   = blockIdx.x;
    const int tid = threadIdx.x;
    __shared__ float red[256];
    const float v = g_scores[(size_t)b * CC + tid];

    red[tid] = v; __syncthreads();
    for (int st = 128; st > 0; st >>= 1) {
        if (tid < st) red[tid] += red[tid + st];
        __syncthreads();
    }
    const float mu = red[0] * (1.f / CC); __syncthreads();
    const float d = v - mu;
    red[tid] = d * d; __syncthreads();
    for (int st = 128; st > 0; st >>= 1) {
        if (tid < st) red[tid] += red[tid + st];
        __syncthreads();
    }
    const float var = red[0] * (1.f / CC);
    out[(size_t)b * CC + tid] = d * rsqrtf(var + LN_EPS) * gamma[tid] + beta[tid];
}

// ---------------------------------------------------------------------------
extern "C" void kernel_launch(void* const* d_in, const int* in_sizes, int n_in,
                              void* d_out, int out_size)
{
    const float* x     = (const float*)d_in[0];
    const float* W1    = (const float*)d_in[1];
    const float* b1    = (const float*)d_in[2];
    const float* w2    = (const float*)d_in[3];
    const float* Wo    = (const float*)d_in[4];
    const float* bo    = (const float*)d_in[5];
    const float* gamma = (const float*)d_in[6];
    const float* beta  = (const float*)d_in[7];

    float* out = (float*)d_out;           // (B, C)
    float* wts = out + BB * CC;           // (B, H, T)

    cudaFuncSetAttribute(k_scores_mma, cudaFuncAttributeMaxDynamicSharedMemorySize,
                         SMEM_SC_TOTAL);

    k_prepw     <<<HH, 256>>>(W1);
    k_scores_mma<<<dim3(TT / 128, BB), 256, SMEM_SC_TOTAL>>>(x, b1, w2);
    k_softmax   <<<BB * HH, 256>>>(wts);
    k_ctx       <<<dim3(NSPLIT, BB), 256>>>(x, wts);
    k_proj      <<<dim3(8, BB), 256>>>(Wo, bo);
    k_ln        <<<BB, 256>>>(gamma, beta, out);
}